// round 3
// baseline (speedup 1.0000x reference)
#include <cuda_runtime.h>
#include <mma.h>

using namespace nvcuda;

// Problem constants
#define BATCH 4096
#define NB    64
#define IB    256
#define OB    256
#define DIN   16384   // NB*IB
#define DOUT  16384   // NB*OB

// Tiling
#define BM  128
#define BN  64
#define BK  32
#define LDA 40        // BK + 8 pad (multiple of 8 for tf32 wmma)
#define LDC 72        // BN + 8 pad (multiple of 8 for f32 store)

__global__ __launch_bounds__(256, 2)
void block_linear_tf32_kernel(const float* __restrict__ x,
                              const float* __restrict__ w,
                              const float* __restrict__ bias,
                              float* __restrict__ out)
{
    __shared__ union SM {
        struct { float A[BM][LDA]; float B[BN][LDA]; } ld;
        float C[BM][LDC];
    } sm;

    const int mTile = blockIdx.x;     // 0..31  (batch tiles of 128)
    const int yTile = blockIdx.y;     // 0..255 (nb * 4 + out-64-tile)
    const int nb    = yTile >> 2;     // which diagonal block
    const int ot    = yTile & 3;      // which 64-wide slice of OUT_BLOCK

    const int tid    = threadIdx.x;
    const int warpId = tid >> 5;
    const int warp_m = warpId & 3;    // 0..3 -> 32-row slice of BM
    const int warp_n = warpId >> 2;   // 0..1 -> 32-col slice of BN

    const float* xBase = x + (size_t)(mTile * BM) * DIN + nb * IB;
    const float* wBase = w + (size_t)nb * OB * IB + (size_t)(ot * BN) * IB;

    wmma::fragment<wmma::accumulator, 16, 16, 8, float> acc[2][2];
    #pragma unroll
    for (int i = 0; i < 2; i++)
        #pragma unroll
        for (int j = 0; j < 2; j++)
            wmma::fill_fragment(acc[i][j], 0.0f);

    for (int k0 = 0; k0 < IB; k0 += BK) {
        // ---- Load A tile: 128 rows x 32 cols of x (float4 vectorized) ----
        #pragma unroll
        for (int v = 0; v < 4; v++) {
            int lin = v * 256 + tid;        // 1024 float4 total
            int r   = lin >> 3;             // row 0..127
            int c4  = lin & 7;              // float4 column 0..7
            float4 val = *(const float4*)(xBase + (size_t)r * DIN + k0 + c4 * 4);
            *(float4*)(&sm.ld.A[r][c4 * 4]) = val;
        }
        // ---- Load B tile: 64 out-rows x 32 in-cols of weight ----
        #pragma unroll
        for (int v = 0; v < 2; v++) {
            int lin = v * 256 + tid;        // 512 float4 total
            int r   = lin >> 3;             // out row 0..63
            int c4  = lin & 7;
            float4 val = *(const float4*)(wBase + (size_t)r * IB + k0 + c4 * 4);
            *(float4*)(&sm.ld.B[r][c4 * 4]) = val;
        }
        __syncthreads();

        // ---- Compute: 4 k-steps of m16n16k8 tf32 ----
        #pragma unroll
        for (int kk = 0; kk < BK; kk += 8) {
            wmma::fragment<wmma::matrix_a, 16, 16, 8, wmma::precision::tf32, wmma::row_major> af[2];
            wmma::fragment<wmma::matrix_b, 16, 16, 8, wmma::precision::tf32, wmma::col_major> bf[2];
            #pragma unroll
            for (int i = 0; i < 2; i++) {
                wmma::load_matrix_sync(af[i], &sm.ld.A[warp_m * 32 + i * 16][kk], LDA);
                #pragma unroll
                for (int t = 0; t < af[i].num_elements; t++)
                    af[i].x[t] = wmma::__float_to_tf32(af[i].x[t]);
            }
            #pragma unroll
            for (int j = 0; j < 2; j++) {
                // B stored as [n][k] (k contiguous) == col_major k x n with ld = LDA
                wmma::load_matrix_sync(bf[j], &sm.ld.B[warp_n * 32 + j * 16][kk], LDA);
                #pragma unroll
                for (int t = 0; t < bf[j].num_elements; t++)
                    bf[j].x[t] = wmma::__float_to_tf32(bf[j].x[t]);
            }
            #pragma unroll
            for (int i = 0; i < 2; i++)
                #pragma unroll
                for (int j = 0; j < 2; j++)
                    wmma::mma_sync(acc[i][j], af[i], bf[j], acc[i][j]);
        }
        __syncthreads();
    }

    // ---- Epilogue: stage through shared, add bias, coalesced float4 store ----
    #pragma unroll
    for (int i = 0; i < 2; i++)
        #pragma unroll
        for (int j = 0; j < 2; j++)
            wmma::store_matrix_sync(&sm.C[warp_m * 32 + i * 16][warp_n * 32 + j * 16],
                                    acc[i][j], LDC, wmma::mem_row_major);
    __syncthreads();

    const float* biasBase = bias + nb * OB + ot * BN;
    float* outBase = out + (size_t)(mTile * BM) * DOUT + nb * OB + ot * BN;

    #pragma unroll
    for (int v = 0; v < 8; v++) {
        int lin = v * 256 + tid;            // 2048 float4 total (128x64)
        int r   = lin >> 4;                 // row 0..127
        int c4  = lin & 15;                 // float4 col 0..15
        float4 val = *(float4*)(&sm.C[r][c4 * 4]);
        float4 bv  = *(const float4*)(biasBase + c4 * 4);
        val.x += bv.x; val.y += bv.y; val.z += bv.z; val.w += bv.w;
        *(float4*)(outBase + (size_t)r * DOUT + c4 * 4) = val;
    }
}

extern "C" void kernel_launch(void* const* d_in, const int* in_sizes, int n_in,
                              void* d_out, int out_size)
{
    const float* x    = (const float*)d_in[0];
    const float* w    = (const float*)d_in[1];
    const float* bias = (const float*)d_in[2];
    float* out        = (float*)d_out;

    dim3 grid(BATCH / BM, NB * (OB / BN));   // (32, 256)
    block_linear_tf32_kernel<<<grid, 256>>>(x, w, bias, out);
}

// round 7
// speedup vs baseline: 2.1534x; 2.1534x over previous
#include <cuda_runtime.h>
#include <cuda_fp16.h>
#include <mma.h>

using namespace nvcuda;

// Problem constants
#define BATCH 4096
#define NB    64
#define IB    256
#define OB    256
#define DIN   16384
#define DOUT  16384

// Tiling
#define BM      128
#define BN      256
#define BK      32
#define THREADS 512
#define LDAH    40      // halves per smem row (32 + 8 pad)
#define LDC     264     // floats per C-staging row (256 + 8 pad)

#define A_STAGE_BYTES (BM * LDAH * 2)                 // 10240
#define B_STAGE_BYTES (BN * LDAH * 2)                 // 20480
#define STAGE_BYTES   (A_STAGE_BYTES + B_STAGE_BYTES) // 30720
#define C_BYTES       (BM * LDC * 4)                  // 135168
#define SMEM_TOTAL    C_BYTES                         // C aliases the 2 load stages

#define NSTAGES (IB / BK)   // 8

__global__ __launch_bounds__(THREADS, 1)
void block_linear_fp16_kernel(const float* __restrict__ x,
                              const float* __restrict__ w,
                              const float* __restrict__ bias,
                              float* __restrict__ out)
{
    extern __shared__ char smem[];
    // Two load stages; C staging aliases them (used only after mainloop).
    half*  sA[2] = { (half*)(smem),
                     (half*)(smem + STAGE_BYTES) };
    half*  sB[2] = { (half*)(smem + A_STAGE_BYTES),
                     (half*)(smem + STAGE_BYTES + A_STAGE_BYTES) };
    float* sC    = (float*)smem;

    const int tid   = threadIdx.x;
    const int wid   = tid >> 5;
    const int mtile = blockIdx.x;   // 0..31
    const int nb    = blockIdx.y;   // 0..63

    const int warp_m = wid & 3;     // 0..3 -> 32-row slice
    const int warp_n = wid >> 2;    // 0..3 -> 64-col slice

    const float* xBase = x + (size_t)mtile * BM * DIN + (size_t)nb * IB;
    const float* wBase = w + (size_t)nb * OB * IB;

    // Per-thread load assignment (float4 granularity):
    //   A: 128 rows x 8 float4 = 1024  -> 2 per thread
    //   B: 256 rows x 8 float4 = 2048  -> 4 per thread
    int aR[2], aC[2], bR[4], bC[4];
    #pragma unroll
    for (int v = 0; v < 2; v++) { int lin = v * THREADS + tid; aR[v] = lin >> 3; aC[v] = lin & 7; }
    #pragma unroll
    for (int v = 0; v < 4; v++) { int lin = v * THREADS + tid; bR[v] = lin >> 3; bC[v] = lin & 7; }

    wmma::fragment<wmma::accumulator, 16, 16, 16, float> acc[2][4];
    #pragma unroll
    for (int i = 0; i < 2; i++)
        #pragma unroll
        for (int j = 0; j < 4; j++)
            wmma::fill_fragment(acc[i][j], 0.0f);

    float4 ra[2], rb[4];

    // ---- Prologue: load + convert stage 0 ----
    #pragma unroll
    for (int v = 0; v < 2; v++)
        ra[v] = *(const float4*)(xBase + (size_t)aR[v] * DIN + aC[v] * 4);
    #pragma unroll
    for (int v = 0; v < 4; v++)
        rb[v] = *(const float4*)(wBase + (size_t)bR[v] * IB + bC[v] * 4);
    #pragma unroll
    for (int v = 0; v < 2; v++) {
        half2* p = (half2*)&sA[0][aR[v] * LDAH + aC[v] * 4];
        p[0] = __floats2half2_rn(ra[v].x, ra[v].y);
        p[1] = __floats2half2_rn(ra[v].z, ra[v].w);
    }
    #pragma unroll
    for (int v = 0; v < 4; v++) {
        half2* p = (half2*)&sB[0][bR[v] * LDAH + bC[v] * 4];
        p[0] = __floats2half2_rn(rb[v].x, rb[v].y);
        p[1] = __floats2half2_rn(rb[v].z, rb[v].w);
    }
    __syncthreads();

    // ---- Mainloop over K ----
    for (int it = 0; it < NSTAGES; it++) {
        const int s = it & 1;

        // Prefetch next stage into registers (overlaps with MMA below)
        if (it + 1 < NSTAGES) {
            const int k0 = (it + 1) * BK;
            #pragma unroll
            for (int v = 0; v < 2; v++)
                ra[v] = *(const float4*)(xBase + (size_t)aR[v] * DIN + k0 + aC[v] * 4);
            #pragma unroll
            for (int v = 0; v < 4; v++)
                rb[v] = *(const float4*)(wBase + (size_t)bR[v] * IB + k0 + bC[v] * 4);
        }

        // Compute current stage: 2 x k16 steps
        #pragma unroll
        for (int kk = 0; kk < BK; kk += 16) {
            wmma::fragment<wmma::matrix_a, 16, 16, 16, half, wmma::row_major> af[2];
            #pragma unroll
            for (int i = 0; i < 2; i++)
                wmma::load_matrix_sync(af[i], &sA[s][(warp_m * 32 + i * 16) * LDAH + kk], LDAH);
            #pragma unroll
            for (int j = 0; j < 4; j++) {
                wmma::fragment<wmma::matrix_b, 16, 16, 16, half, wmma::col_major> bf;
                // B smem is [n][k] (k contiguous) == col_major (k x n), ld = LDAH
                wmma::load_matrix_sync(bf, &sB[s][(warp_n * 64 + j * 16) * LDAH + kk], LDAH);
                wmma::mma_sync(acc[0][j], af[0], bf, acc[0][j]);
                wmma::mma_sync(acc[1][j], af[1], bf, acc[1][j]);
            }
        }

        // Convert + store next stage, then barrier
        if (it + 1 < NSTAGES) {
            const int d = s ^ 1;
            #pragma unroll
            for (int v = 0; v < 2; v++) {
                half2* p = (half2*)&sA[d][aR[v] * LDAH + aC[v] * 4];
                p[0] = __floats2half2_rn(ra[v].x, ra[v].y);
                p[1] = __floats2half2_rn(ra[v].z, ra[v].w);
            }
            #pragma unroll
            for (int v = 0; v < 4; v++) {
                half2* p = (half2*)&sB[d][bR[v] * LDAH + bC[v] * 4];
                p[0] = __floats2half2_rn(rb[v].x, rb[v].y);
                p[1] = __floats2half2_rn(rb[v].z, rb[v].w);
            }
            __syncthreads();
        }
    }

    // All MMA shared reads must finish before C staging overwrites the buffers
    __syncthreads();

    // ---- Epilogue: frags -> shared, bias add, coalesced float4 stores ----
    #pragma unroll
    for (int i = 0; i < 2; i++)
        #pragma unroll
        for (int j = 0; j < 4; j++)
            wmma::store_matrix_sync(&sC[(warp_m * 32 + i * 16) * LDC + warp_n * 64 + j * 16],
                                    acc[i][j], LDC, wmma::mem_row_major);
    __syncthreads();

    const float* biasBase = bias + (size_t)nb * OB;
    float* outBase = out + (size_t)(mtile * BM) * DOUT + (size_t)nb * OB;

    // 128 rows x 64 float4 = 8192 float4 -> 16 per thread
    #pragma unroll
    for (int v = 0; v < 16; v++) {
        int lin = v * THREADS + tid;
        int r   = lin >> 6;        // 0..127
        int c4  = lin & 63;        // 0..63
        float4 val = *(float4*)(&sC[r * LDC + c4 * 4]);
        float4 bv  = *(const float4*)(biasBase + c4 * 4);
        val.x += bv.x; val.y += bv.y; val.z += bv.z; val.w += bv.w;
        *(float4*)(outBase + (size_t)r * DOUT + c4 * 4) = val;
    }
}

extern "C" void kernel_launch(void* const* d_in, const int* in_sizes, int n_in,
                              void* d_out, int out_size)
{
    const float* x    = (const float*)d_in[0];
    const float* w    = (const float*)d_in[1];
    const float* bias = (const float*)d_in[2];
    float* out        = (float*)d_out;

    static bool configured = false;
    if (!configured) {
        cudaFuncSetAttribute(block_linear_fp16_kernel,
                             cudaFuncAttributeMaxDynamicSharedMemorySize, SMEM_TOTAL);
        configured = true;
    }

    dim3 grid(BATCH / BM, NB);   // (32, 64) = 2048 CTAs
    block_linear_fp16_kernel<<<grid, THREADS, SMEM_TOTAL>>>(x, w, bias, out);
}

// round 12
// speedup vs baseline: 2.4431x; 1.1346x over previous
#include <cuda_runtime.h>
#include <cuda_fp16.h>
#include <mma.h>
#include <cstdint>

using namespace nvcuda;

// Problem constants
#define BATCH 4096
#define NB    64
#define IB    256
#define OB    256
#define DIN   16384
#define DOUT  16384

// GEMM tiling
#define BM      128
#define BN      128
#define BK      32
#define THREADS 256
#define LDAH    40                      // halves per smem row (32 + 8 pad) -> 80B stride
#define LDC     136                     // floats per C-staging row (128 + 8 pad)

#define A_STAGE_BYTES (BM * LDAH * 2)   // 10240
#define B_STAGE_BYTES (BN * LDAH * 2)   // 10240
#define NSTAGES       (IB / BK)         // 8

// smem: [ A0 | A1 | B0 | B1 | B2 ]  aliased by C staging
#define SMEM_LOAD_BYTES (2 * A_STAGE_BYTES + 3 * B_STAGE_BYTES)   // 51200
#define C_BYTES         (BM * LDC * 4)                            // 69632
#define SMEM_TOTAL      (C_BYTES > SMEM_LOAD_BYTES ? C_BYTES : SMEM_LOAD_BYTES)

// fp16 weight copy (filled by prepass each launch; deterministic)
__device__ __half w16_g[NB * OB * IB];   // 8 MB

__device__ __forceinline__ void cp16(uint32_t s, const void* g) {
    asm volatile("cp.async.cg.shared.global [%0], [%1], 16;\n" :: "r"(s), "l"(g));
}

// ---------------- Prepass: weight fp32 -> fp16 ----------------
__global__ void convert_w_kernel(const float* __restrict__ w) {
    // 64*256*256 = 4194304 halves; each thread converts 8 (two float4 -> one 16B store)
    int idx = blockIdx.x * blockDim.x + threadIdx.x;   // 0 .. 524287
    const float4* src = (const float4*)(w) + idx * 2;
    float4 a = src[0], b = src[1];
    half2 h[4];
    h[0] = __floats2half2_rn(a.x, a.y);
    h[1] = __floats2half2_rn(a.z, a.w);
    h[2] = __floats2half2_rn(b.x, b.y);
    h[3] = __floats2half2_rn(b.z, b.w);
    *((uint4*)(w16_g) + idx) = *(const uint4*)h;
}

// ---------------- Main GEMM ----------------
__global__ __launch_bounds__(THREADS, 2)
void block_linear_fp16_kernel(const float* __restrict__ x,
                              const float* __restrict__ bias,
                              float* __restrict__ out)
{
    extern __shared__ char smem[];
    half*  sA[2] = { (half*)(smem), (half*)(smem + A_STAGE_BYTES) };
    half*  sB[3] = { (half*)(smem + 2 * A_STAGE_BYTES),
                     (half*)(smem + 2 * A_STAGE_BYTES + B_STAGE_BYTES),
                     (half*)(smem + 2 * A_STAGE_BYTES + 2 * B_STAGE_BYTES) };
    float* sC    = (float*)smem;
    const uint32_t sBu[3] = { (uint32_t)__cvta_generic_to_shared(sB[0]),
                              (uint32_t)__cvta_generic_to_shared(sB[1]),
                              (uint32_t)__cvta_generic_to_shared(sB[2]) };

    const int tid   = threadIdx.x;
    const int wid   = tid >> 5;
    const int mtile = blockIdx.x;          // 0..31
    const int nbot  = blockIdx.y;          // 0..127
    const int nb    = nbot >> 1;           // diagonal block
    const int ot    = nbot & 1;            // out half (128 cols)

    const int warp_m = wid & 3;            // 4 x 32 rows
    const int warp_n = wid >> 2;           // 2 x 64 cols

    const float* xBase  = x + (size_t)mtile * BM * DIN + (size_t)nb * IB;
    const half*  wBase  = w16_g + (size_t)nb * OB * IB + (size_t)(ot * BN) * IB;

    // A: 128 rows x 8 float4 = 1024 -> 4 per thread
    int aR[4], aC[4];
    #pragma unroll
    for (int v = 0; v < 4; v++) { int lin = v * THREADS + tid; aR[v] = lin >> 3; aC[v] = lin & 7; }
    // B cp.async: 128 rows x 4 x 16B chunks = 512 -> 2 per thread
    int bN[2], bC[2];
    #pragma unroll
    for (int v = 0; v < 2; v++) { int lin = v * THREADS + tid; bN[v] = lin >> 2; bC[v] = lin & 3; }

    wmma::fragment<wmma::accumulator, 16, 16, 16, float> acc[2][4];
    #pragma unroll
    for (int i = 0; i < 2; i++)
        #pragma unroll
        for (int j = 0; j < 4; j++)
            wmma::fill_fragment(acc[i][j], 0.0f);

    // ---- Prologue ----
    // Issue B stage 0 and 1
    #pragma unroll
    for (int st = 0; st < 2; st++) {
        #pragma unroll
        for (int v = 0; v < 2; v++)
            cp16(sBu[st] + bN[v] * 80 + bC[v] * 16,
                 wBase + (size_t)bN[v] * IB + st * BK + bC[v] * 8);
        asm volatile("cp.async.commit_group;\n" ::: "memory");
    }
    // A stage 0: LDG + convert + STS
    float4 ra[4];
    #pragma unroll
    for (int v = 0; v < 4; v++)
        ra[v] = *(const float4*)(xBase + (size_t)aR[v] * DIN + aC[v] * 4);
    #pragma unroll
    for (int v = 0; v < 4; v++) {
        half2* p = (half2*)&sA[0][aR[v] * LDAH + aC[v] * 4];
        p[0] = __floats2half2_rn(ra[v].x, ra[v].y);
        p[1] = __floats2half2_rn(ra[v].z, ra[v].w);
    }
    asm volatile("cp.async.wait_group 1;\n" ::: "memory");   // B0 arrived
    __syncthreads();

    // ---- Mainloop ----
    #pragma unroll
    for (int it = 0; it < NSTAGES; it++) {
        const int s2 = it & 1;
        const int s3 = it % 3;

        // Prefetch next A into registers (overlaps MMA)
        if (it + 1 < NSTAGES) {
            const int k0 = (it + 1) * BK;
            #pragma unroll
            for (int v = 0; v < 4; v++)
                ra[v] = *(const float4*)(xBase + (size_t)aR[v] * DIN + k0 + aC[v] * 4);
        }

        // Compute: 2 x k16 steps, warp tile 32x64
        #pragma unroll
        for (int kk = 0; kk < BK; kk += 16) {
            wmma::fragment<wmma::matrix_a, 16, 16, 16, half, wmma::row_major> af[2];
            #pragma unroll
            for (int i = 0; i < 2; i++)
                wmma::load_matrix_sync(af[i], &sA[s2][(warp_m * 32 + i * 16) * LDAH + kk], LDAH);
            #pragma unroll
            for (int j = 0; j < 4; j++) {
                wmma::fragment<wmma::matrix_b, 16, 16, 16, half, wmma::col_major> bf;
                wmma::load_matrix_sync(bf, &sB[s3][(warp_n * 64 + j * 16) * LDAH + kk], LDAH);
                wmma::mma_sync(acc[0][j], af[0], bf, acc[0][j]);
                wmma::mma_sync(acc[1][j], af[1], bf, acc[1][j]);
            }
        }

        if (it + 1 < NSTAGES) {
            // Convert + store next A stage
            #pragma unroll
            for (int v = 0; v < 4; v++) {
                half2* p = (half2*)&sA[s2 ^ 1][aR[v] * LDAH + aC[v] * 4];
                p[0] = __floats2half2_rn(ra[v].x, ra[v].y);
                p[1] = __floats2half2_rn(ra[v].z, ra[v].w);
            }
            // Issue B for it+2 into stage (it+2)%3 (consumed at it-1; safe pre-sync)
            if (it + 2 < NSTAGES) {
                const int st = (it + 2) % 3;
                const int k0 = (it + 2) * BK;
                #pragma unroll
                for (int v = 0; v < 2; v++)
                    cp16(sBu[st] + bN[v] * 80 + bC[v] * 16,
                         wBase + (size_t)bN[v] * IB + k0 + bC[v] * 8);
                asm volatile("cp.async.commit_group;\n" ::: "memory");
                asm volatile("cp.async.wait_group 1;\n" ::: "memory");  // B(it+1) arrived
            } else {
                asm volatile("cp.async.wait_group 0;\n" ::: "memory");
            }
            __syncthreads();
        }
    }

    // ---- Epilogue: stage C through shared (aliases load buffers) ----
    __syncthreads();
    #pragma unroll
    for (int i = 0; i < 2; i++)
        #pragma unroll
        for (int j = 0; j < 4; j++)
            wmma::store_matrix_sync(&sC[(warp_m * 32 + i * 16) * LDC + warp_n * 64 + j * 16],
                                    acc[i][j], LDC, wmma::mem_row_major);
    __syncthreads();

    const float* biasBase = bias + (size_t)nb * OB + ot * BN;
    float* outBase = out + (size_t)(mtile * BM) * DOUT + (size_t)nb * OB + ot * BN;

    // 128 rows x 32 float4 = 4096 -> 16 per thread
    #pragma unroll
    for (int v = 0; v < 16; v++) {
        int lin = v * THREADS + tid;
        int r   = lin >> 5;       // 0..127
        int c4  = lin & 31;       // 0..31
        float4 val = *(float4*)(&sC[r * LDC + c4 * 4]);
        float4 bv  = *(const float4*)(biasBase + c4 * 4);
        val.x += bv.x; val.y += bv.y; val.z += bv.z; val.w += bv.w;
        *(float4*)(outBase + (size_t)r * DOUT + c4 * 4) = val;
    }
}

extern "C" void kernel_launch(void* const* d_in, const int* in_sizes, int n_in,
                              void* d_out, int out_size)
{
    const float* x    = (const float*)d_in[0];
    const float* w    = (const float*)d_in[1];
    const float* bias = (const float*)d_in[2];
    float* out        = (float*)d_out;

    // Unconditional (no static guards per harness rules); cheap and capture-safe.
    cudaFuncSetAttribute(block_linear_fp16_kernel,
                         cudaFuncAttributeMaxDynamicSharedMemorySize, SMEM_TOTAL);

    // Prepass: convert weights to fp16 (4194304/8 = 524288 threads)
    convert_w_kernel<<<2048, 256>>>(w);

    dim3 grid(BATCH / BM, NB * (OB / BN));   // (32, 128) = 4096 CTAs
    block_linear_fp16_kernel<<<grid, THREADS, SMEM_TOTAL>>>(x, bias, out);
}